// round 8
// baseline (speedup 1.0000x reference)
#include <cuda_runtime.h>
#include <math.h>

#define TT 512
#define BB 128
#define II 256
#define HH 1024
#define OO 256
#define GG 4096   // 4*H
#define NB 128    // persistent blocks (<= 148 SMs -> single wave)

// ---------------- device scratch (static, graph-safe) ----------------
__device__ float g_h[BB * HH];
__device__ float g_c[BB * HH];
__device__ float g_gates[BB * GG];
__device__ float g_tmp[BB * HH];
__device__ float g_context[BB * HH];
__device__ float g_hWh[BB * HH];
__device__ float g_scores[TT * BB];
__device__ float g_wts[TT * BB];
__device__ float g_bias_dec[GG];
__device__ float g_ctx_seq[(size_t)TT * BB * HH];   // 268 MB
__device__ float g_ctx_proj[(size_t)TT * BB * HH];  // 268 MB
__device__ float g_xw[(size_t)TT * BB * GG];        // 1.07 GB: x@W_ih^T + biases

// ---------------- packed f32x2 helpers ----------------
#define FMA2(acc, a, b)  asm("fma.rn.f32x2 %0, %1, %2, %0;" : "+l"(acc) : "l"(a), "l"(b))
#define UNPK2(lo, hi, v) asm("mov.b64 {%0, %1}, %2;" : "=f"(lo), "=f"(hi) : "l"(v))

// fast tanh: 1 - 2/(exp(2x)+1), ex2.approx + rcp.approx (abs err ~1e-7)
__device__ __forceinline__ float ftanh(float x)
{
    float e, r;
    asm("ex2.approx.f32 %0, %1;" : "=f"(e) : "f"(x * 2.8853900817779268f));
    asm("rcp.approx.f32 %0, %1;" : "=f"(r) : "f"(e + 1.0f));
    return fmaf(-2.0f, r, 1.0f);
}

// ---------------- software grid barrier ----------------
__device__ int g_bar_count;
__device__ int g_bar_gen;

__device__ __forceinline__ void grid_sync_sw()
{
    __syncthreads();
    if (threadIdx.x == 0) {
        int gen = *(volatile int*)&g_bar_gen;   // read before arriving
        __threadfence();
        if (atomicAdd(&g_bar_count, 1) == NB - 1) {
            g_bar_count = 0;
            __threadfence();
            atomicExch(&g_bar_gen, gen + 1);
        } else {
            while (*(volatile int*)&g_bar_gen == gen) { __nanosleep(32); }
        }
    }
    __syncthreads();
}

__device__ __forceinline__ float sigf(float x) { return 1.f / (1.f + expf(-x)); }

// =====================================================================
// Parallel GEMM: C = A @ W^T (+bias1)(+bias2), 64x64 tiles, 256 thr.
// A-tile stored DUPLICATED in smem -> LDS.128 gives 2 packed {a,a} splats.
// =====================================================================
__global__ __launch_bounds__(256) void par_gemm(
    const float* __restrict__ A, int lda,
    const float* __restrict__ W, int ldw, int woff, int K,
    const float* __restrict__ bias1, const float* __restrict__ bias2,
    float* __restrict__ C, int ldc)
{
    __shared__ __align__(16) float As[16][136];  // duplicated rows (64*2 + pad)
    __shared__ __align__(16) float Bs[16][68];
    const int tid  = threadIdx.x;
    const int tx   = tid & 15;
    const int ty   = tid >> 4;
    const int bn   = blockIdx.x * 64;
    const int bm   = blockIdx.y * 64;
    const int lrow = tid >> 2;
    const int lcol = (tid & 3) << 2;

    unsigned long long acc2[4][2] = {};

    for (int k0 = 0; k0 < K; k0 += 16) {
        float4 av = *(const float4*)(A + (size_t)(bm + lrow) * lda + k0 + lcol);
        float4 wv = *(const float4*)(W + (size_t)(bn + lrow) * ldw + woff + k0 + lcol);
        __syncthreads();
        *(float2*)&As[lcol + 0][2 * lrow] = make_float2(av.x, av.x);
        *(float2*)&As[lcol + 1][2 * lrow] = make_float2(av.y, av.y);
        *(float2*)&As[lcol + 2][2 * lrow] = make_float2(av.z, av.z);
        *(float2*)&As[lcol + 3][2 * lrow] = make_float2(av.w, av.w);
        Bs[lcol + 0][lrow] = wv.x; Bs[lcol + 1][lrow] = wv.y;
        Bs[lcol + 2][lrow] = wv.z; Bs[lcol + 3][lrow] = wv.w;
        __syncthreads();
        #pragma unroll
        for (int kk = 0; kk < 16; ++kk) {
            ulonglong2 a01 = *(const ulonglong2*)&As[kk][ty << 3];
            ulonglong2 a23 = *(const ulonglong2*)&As[kk][(ty << 3) + 4];
            ulonglong2 b   = *(const ulonglong2*)&Bs[kk][tx << 2];
            FMA2(acc2[0][0], a01.x, b.x); FMA2(acc2[0][1], a01.x, b.y);
            FMA2(acc2[1][0], a01.y, b.x); FMA2(acc2[1][1], a01.y, b.y);
            FMA2(acc2[2][0], a23.x, b.x); FMA2(acc2[2][1], a23.x, b.y);
            FMA2(acc2[3][0], a23.y, b.x); FMA2(acc2[3][1], a23.y, b.y);
        }
    }

    const int m0 = bm + (ty << 2);
    const int n0 = bn + (tx << 2);
    float4 bv = make_float4(0.f, 0.f, 0.f, 0.f);
    if (bias1) {
        float4 b1 = *(const float4*)(bias1 + n0);
        bv.x += b1.x; bv.y += b1.y; bv.z += b1.z; bv.w += b1.w;
    }
    if (bias2) {
        float4 b2 = *(const float4*)(bias2 + n0);
        bv.x += b2.x; bv.y += b2.y; bv.z += b2.z; bv.w += b2.w;
    }
    #pragma unroll
    for (int i = 0; i < 4; ++i) {
        float4 r;
        UNPK2(r.x, r.y, acc2[i][0]);
        UNPK2(r.z, r.w, acc2[i][1]);
        r.x += bv.x; r.y += bv.y; r.z += bv.z; r.w += bv.w;
        *(float4*)(C + (size_t)(m0 + i) * ldc + n0) = r;
    }
}

// =====================================================================
// Persistent encoder: 512 steps of h@W_hh + fused LSTM cell.
// Block tile: 32 batch x 128 gate-cols, 512 thr, double-buffered, dup-A.
// =====================================================================
__global__ __launch_bounds__(512) void encoder_kernel(
    const float* __restrict__ W_hh,
    const float* __restrict__ bihd, const float* __restrict__ bhhd)
{
    __shared__ __align__(16) float As[2][16][68];   // [buf][k][2m dup]
    __shared__ __align__(16) float Bs[2][16][132];  // [buf][k][n]
    __shared__ __align__(16) float Gs[32][132];     // gate tile for cell

    const int tid = threadIdx.x;
    const int bid = blockIdx.x;

    for (int i = bid * 512 + tid; i < BB * HH; i += NB * 512) { g_h[i] = 0.f; g_c[i] = 0.f; }
    for (int i = bid * 512 + tid; i < GG; i += NB * 512) g_bias_dec[i] = bihd[i] + bhhd[i];
    grid_sync_sw();

    const int bm  = (bid >> 5) * 32;
    const int hh0 = (bid & 31) * 32;
    const int tx  = tid & 31;          // n group: n0 = tx*4
    const int ty  = tid >> 5;          // 0..15: rows 2ty, 2ty+1

    const int ln = tid >> 2;                         // 0..127
    const int lk = (tid & 3) << 2;
    const float* wbase = W_hh + (size_t)((ln >> 5) * HH + hh0 + (ln & 31)) * HH + lk;
    const int arow = tid >> 2;                       // 0..31 for tid<128
    const float* abase = g_h + (size_t)(bm + arow) * HH + lk;

    const int n0 = tx << 2;
    const int gate = n0 >> 5;
    const int within = n0 & 31;
    const size_t xwcol = (size_t)gate * HH + hh0 + within;

    for (int t = 0; t < TT; ++t) {
        float4 wv = *(const float4*)(wbase);
        float4 av = (tid < 128) ? *(const float4*)(abase) : make_float4(0, 0, 0, 0);

        unsigned long long acc2[2][2] = {};
        int buf = 0;
        {
            Bs[0][lk + 0][ln] = wv.x; Bs[0][lk + 1][ln] = wv.y;
            Bs[0][lk + 2][ln] = wv.z; Bs[0][lk + 3][ln] = wv.w;
            if (tid < 128) {
                *(float2*)&As[0][lk + 0][2 * arow] = make_float2(av.x, av.x);
                *(float2*)&As[0][lk + 1][2 * arow] = make_float2(av.y, av.y);
                *(float2*)&As[0][lk + 2][2 * arow] = make_float2(av.z, av.z);
                *(float2*)&As[0][lk + 3][2 * arow] = make_float2(av.w, av.w);
            }
        }
        __syncthreads();

        #pragma unroll 1
        for (int kt = 0; kt < 64; ++kt) {
            if (kt < 63) {
                wv = *(const float4*)(wbase + (kt + 1) * 16);
                if (tid < 128) av = *(const float4*)(abase + (kt + 1) * 16);
            }
            #pragma unroll
            for (int kk = 0; kk < 16; ++kk) {
                ulonglong2 a = *(const ulonglong2*)&As[buf][kk][ty << 2]; // 2 splats
                ulonglong2 b = *(const ulonglong2*)&Bs[buf][kk][n0];     // 2 pairs
                FMA2(acc2[0][0], a.x, b.x); FMA2(acc2[0][1], a.x, b.y);
                FMA2(acc2[1][0], a.y, b.x); FMA2(acc2[1][1], a.y, b.y);
            }
            if (kt < 63) {
                buf ^= 1;
                Bs[buf][lk + 0][ln] = wv.x; Bs[buf][lk + 1][ln] = wv.y;
                Bs[buf][lk + 2][ln] = wv.z; Bs[buf][lk + 3][ln] = wv.w;
                if (tid < 128) {
                    *(float2*)&As[buf][lk + 0][2 * arow] = make_float2(av.x, av.x);
                    *(float2*)&As[buf][lk + 1][2 * arow] = make_float2(av.y, av.y);
                    *(float2*)&As[buf][lk + 2][2 * arow] = make_float2(av.z, av.z);
                    *(float2*)&As[buf][lk + 3][2 * arow] = make_float2(av.w, av.w);
                }
                __syncthreads();
            }
        }

        // epilogue: add precomputed xW (biases folded), stage gates
        {
            const float* xwp = g_xw + ((size_t)t * BB + bm) * GG + xwcol;
            #pragma unroll
            for (int i = 0; i < 2; ++i) {
                int m = (ty << 1) + i;
                float4 x4 = *(const float4*)(xwp + (size_t)m * GG);
                float4 r;
                UNPK2(r.x, r.y, acc2[i][0]);
                UNPK2(r.z, r.w, acc2[i][1]);
                r.x += x4.x; r.y += x4.y; r.z += x4.z; r.w += x4.w;
                *(float4*)&Gs[m][n0] = r;
            }
        }
        __syncthreads();

        // fused LSTM cell (accurate transcendentals: recurrent state)
        #pragma unroll
        for (int e = tid; e < 32 * 32; e += 512) {
            int r = e >> 5, hc = e & 31;
            float gi = sigf(Gs[r][hc]);
            float gf = sigf(Gs[r][32 + hc]);
            float gg = tanhf(Gs[r][64 + hc]);
            float go = sigf(Gs[r][96 + hc]);
            size_t idx = (size_t)(bm + r) * HH + hh0 + hc;
            float c = gf * g_c[idx] + gi * gg;
            g_c[idx] = c;
            float h = go * tanhf(c);
            g_h[idx] = h;
            g_ctx_seq[(size_t)t * BB * HH + idx] = h;
        }
        grid_sync_sw();
    }
}

// =====================================================================
// Dual-input 64x64 GEMM tile (decoder gates), 256 threads, dup-A
// =====================================================================
__device__ __forceinline__ void gemm_tile(
    const float* __restrict__ A1, int lda1,
    const float* __restrict__ W1, int ldw1, int K1,
    const float* __restrict__ A2, int lda2,
    const float* __restrict__ W2, int ldw2, int K2,
    const float* __restrict__ bias,
    float* __restrict__ C, int ldc,
    int bm, int bn, float (&As)[16][136], float (&Bs)[16][68])
{
    const int tid  = threadIdx.x;
    const int tx   = tid & 15;
    const int ty   = tid >> 4;
    const int lrow = tid >> 2;
    const int lcol = (tid & 3) << 2;

    unsigned long long acc2[4][2] = {};

    #pragma unroll 1
    for (int ph = 0; ph < 2; ++ph) {
        const float* A  = ph ? A2 : A1;
        const float* W  = ph ? W2 : W1;
        const int lda   = ph ? lda2 : lda1;
        const int ldw   = ph ? ldw2 : ldw1;
        const int K     = ph ? K2 : K1;

        for (int k0 = 0; k0 < K; k0 += 16) {
            float4 av = *(const float4*)(A + (size_t)(bm + lrow) * lda + k0 + lcol);
            float4 wv = *(const float4*)(W + (size_t)(bn + lrow) * ldw + k0 + lcol);
            __syncthreads();
            *(float2*)&As[lcol + 0][2 * lrow] = make_float2(av.x, av.x);
            *(float2*)&As[lcol + 1][2 * lrow] = make_float2(av.y, av.y);
            *(float2*)&As[lcol + 2][2 * lrow] = make_float2(av.z, av.z);
            *(float2*)&As[lcol + 3][2 * lrow] = make_float2(av.w, av.w);
            Bs[lcol + 0][lrow] = wv.x; Bs[lcol + 1][lrow] = wv.y;
            Bs[lcol + 2][lrow] = wv.z; Bs[lcol + 3][lrow] = wv.w;
            __syncthreads();
            #pragma unroll
            for (int kk = 0; kk < 16; ++kk) {
                ulonglong2 a01 = *(const ulonglong2*)&As[kk][ty << 3];
                ulonglong2 a23 = *(const ulonglong2*)&As[kk][(ty << 3) + 4];
                ulonglong2 b   = *(const ulonglong2*)&Bs[kk][tx << 2];
                FMA2(acc2[0][0], a01.x, b.x); FMA2(acc2[0][1], a01.x, b.y);
                FMA2(acc2[1][0], a01.y, b.x); FMA2(acc2[1][1], a01.y, b.y);
                FMA2(acc2[2][0], a23.x, b.x); FMA2(acc2[2][1], a23.x, b.y);
                FMA2(acc2[3][0], a23.y, b.x); FMA2(acc2[3][1], a23.y, b.y);
            }
        }
    }

    const int m0 = bm + (ty << 2);
    const int n0 = bn + (tx << 2);
    float4 bv = bias ? *(const float4*)(bias + n0) : make_float4(0.f, 0.f, 0.f, 0.f);
    #pragma unroll
    for (int i = 0; i < 4; ++i) {
        float4 r;
        UNPK2(r.x, r.y, acc2[i][0]);
        UNPK2(r.z, r.w, acc2[i][1]);
        r.x += bv.x; r.y += bv.y; r.z += bv.z; r.w += bv.w;
        *(float4*)(C + (size_t)(m0 + i) * ldc + n0) = r;
    }
}

// =====================================================================
// 32x64 GEMM tile (decoder small GEMMs), 256 threads, dup-A
// =====================================================================
__device__ __forceinline__ void gemm_tile32(
    const float* __restrict__ A, int lda,
    const float* __restrict__ W, int ldw, int woff, int K,
    const float* __restrict__ bias,
    float* __restrict__ C, int ldc, int do_relu,
    int bm, int bn, float (&As)[16][136], float (&Bs)[16][68])
{
    const int tid  = threadIdx.x;
    const int tx   = tid & 15;
    const int ty   = tid >> 4;
    const int lrow = tid >> 2;           // A: 0..31 (tid<128); W: 0..63
    const int lcol = (tid & 3) << 2;

    unsigned long long acc2[2][2] = {};

    for (int k0 = 0; k0 < K; k0 += 16) {
        float4 av = (tid < 128)
            ? *(const float4*)(A + (size_t)(bm + lrow) * lda + k0 + lcol)
            : make_float4(0, 0, 0, 0);
        float4 wv = *(const float4*)(W + (size_t)(bn + lrow) * ldw + woff + k0 + lcol);
        __syncthreads();
        if (tid < 128) {
            *(float2*)&As[lcol + 0][2 * lrow] = make_float2(av.x, av.x);
            *(float2*)&As[lcol + 1][2 * lrow] = make_float2(av.y, av.y);
            *(float2*)&As[lcol + 2][2 * lrow] = make_float2(av.z, av.z);
            *(float2*)&As[lcol + 3][2 * lrow] = make_float2(av.w, av.w);
        }
        Bs[lcol + 0][lrow] = wv.x; Bs[lcol + 1][lrow] = wv.y;
        Bs[lcol + 2][lrow] = wv.z; Bs[lcol + 3][lrow] = wv.w;
        __syncthreads();
        #pragma unroll
        for (int kk = 0; kk < 16; ++kk) {
            ulonglong2 a = *(const ulonglong2*)&As[kk][ty << 2];  // rows 2ty,2ty+1 splats
            ulonglong2 b = *(const ulonglong2*)&Bs[kk][tx << 2];
            FMA2(acc2[0][0], a.x, b.x); FMA2(acc2[0][1], a.x, b.y);
            FMA2(acc2[1][0], a.y, b.x); FMA2(acc2[1][1], a.y, b.y);
        }
    }

    const int m0 = bm + (ty << 1);
    const int n0 = bn + (tx << 2);
    float4 bv = bias ? *(const float4*)(bias + n0) : make_float4(0.f, 0.f, 0.f, 0.f);
    #pragma unroll
    for (int i = 0; i < 2; ++i) {
        float4 r;
        UNPK2(r.x, r.y, acc2[i][0]);
        UNPK2(r.z, r.w, acc2[i][1]);
        r.x += bv.x; r.y += bv.y; r.z += bv.z; r.w += bv.w;
        if (do_relu) {
            r.x = fmaxf(r.x, 0.f); r.y = fmaxf(r.y, 0.f);
            r.z = fmaxf(r.z, 0.f); r.w = fmaxf(r.w, 0.f);
        }
        *(float4*)(C + (size_t)(m0 + i) * ldc + n0) = r;
    }
}

__device__ __forceinline__ void cell_phase_dec()
{
    for (int idx = blockIdx.x * 256 + threadIdx.x; idx < BB * HH; idx += NB * 256) {
        int b  = idx >> 10;
        int hh = idx & (HH - 1);
        const float* gb = g_gates + (size_t)b * GG;
        float i = sigf(gb[hh]);
        float f = sigf(gb[HH + hh]);
        float g = tanhf(gb[2 * HH + hh]);
        float o = sigf(gb[3 * HH + hh]);
        float c = f * g_c[idx] + i * g;
        g_c[idx] = c;
        g_h[idx] = o * tanhf(c);
    }
}

// =====================================================================
// Persistent decoder. 128 blocks, 256 threads.
// =====================================================================
__global__ __launch_bounds__(256) void decoder_kernel(
    const float* __restrict__ W_attn, const float* __restrict__ v,
    const float* __restrict__ W_ih_dec, const float* __restrict__ W_hh_dec,
    const float* __restrict__ W_dec, const float* __restrict__ b_dec,
    const float* __restrict__ W_out, const float* __restrict__ b_out,
    float* __restrict__ out, int len_out)
{
    __shared__ __align__(16) float As[16][136];
    __shared__ __align__(16) float Bs[16][68];
    __shared__ float red[TT];
    const int bid = blockIdx.x;
    const int tid = threadIdx.x;

    for (int i = bid * 256 + tid; i < BB * HH; i += NB * 256) g_c[i] = 0.f;
    grid_sync_sw();

    for (int s = 0; s < len_out; ++s) {
        // 1: hWh = h @ W_h^T   [64 tiles of 32x64]
        if (bid < 64) {
            gemm_tile32(g_h, HH, W_attn, 2 * HH, 0, HH,
                        nullptr, g_hWh, HH, 0,
                        (bid >> 4) * 32, (bid & 15) * 64, As, Bs);
        }
        grid_sync_sw();

        // 2: scores[t,b] = sum_g ftanh(hWh[b,g]+ctx_proj[t,b,g]) * v[g]
        {
            int w = bid * 8 + (tid >> 5);
            int lane = tid & 31;
            for (int p = w; p < TT * BB; p += NB * 8) {
                int t = p >> 7, b = p & (BB - 1);
                const float* cp = g_ctx_proj + ((size_t)t * BB + b) * HH;
                const float* hw = g_hWh + (size_t)b * HH;
                float sum = 0.f;
                #pragma unroll 2
                for (int g = lane * 4; g < HH; g += 128) {
                    float4 c4 = *(const float4*)(cp + g);
                    float4 h4 = *(const float4*)(hw + g);
                    float4 v4 = *(const float4*)(v + g);
                    sum += ftanh(h4.x + c4.x) * v4.x;
                    sum += ftanh(h4.y + c4.y) * v4.y;
                    sum += ftanh(h4.z + c4.z) * v4.z;
                    sum += ftanh(h4.w + c4.w) * v4.w;
                }
                #pragma unroll
                for (int off = 16; off; off >>= 1)
                    sum += __shfl_down_sync(0xffffffffu, sum, off);
                if (lane == 0) g_scores[p] = sum;
            }
        }
        grid_sync_sw();

        // 3: softmax over t (column b = bid)
        {
            float a  = g_scores[tid * BB + bid];
            float a2 = g_scores[(tid + 256) * BB + bid];
            red[tid] = fmaxf(a, a2);
            __syncthreads();
            for (int off = 128; off; off >>= 1) {
                if (tid < off) red[tid] = fmaxf(red[tid], red[tid + off]);
                __syncthreads();
            }
            float mx = red[0];
            __syncthreads();
            float e1 = expf(a - mx), e2 = expf(a2 - mx);
            red[tid] = e1 + e2;
            __syncthreads();
            for (int off = 128; off; off >>= 1) {
                if (tid < off) red[tid] += red[tid + off];
                __syncthreads();
            }
            float inv = 1.f / red[0];
            g_wts[tid * BB + bid] = e1 * inv;
            g_wts[(tid + 256) * BB + bid] = e2 * inv;
            __syncthreads();
        }
        grid_sync_sw();

        // 4: context[b,h] = sum_t ctx_seq[t,b,h]*w[t,b]; block bid owns b=bid
        {
            for (int t = tid; t < TT; t += 256) red[t] = g_wts[t * BB + bid];
            __syncthreads();
            const int hh = tid * 4;
            const float* base = g_ctx_seq + (size_t)bid * HH + hh;
            float4 sacc = make_float4(0.f, 0.f, 0.f, 0.f);
            #pragma unroll 4
            for (int t = 0; t < TT; ++t) {
                float4 x = *(const float4*)(base + (size_t)t * BB * HH);
                float wt = red[t];
                sacc.x += x.x * wt; sacc.y += x.y * wt;
                sacc.z += x.z * wt; sacc.w += x.w * wt;
            }
            *(float4*)(g_context + bid * HH + hh) = sacc;
            __syncthreads();
        }
        grid_sync_sw();

        // 5: gates = context@W_ih_dec^T + h@W_hh_dec^T + bias  [128 tiles]
        gemm_tile(g_context, HH, W_ih_dec, HH, HH,
                  g_h, HH, W_hh_dec, HH, HH,
                  g_bias_dec, g_gates, GG,
                  (bid >> 6) * 64, (bid & 63) * 64, As, Bs);
        grid_sync_sw();

        // 6: LSTM cell
        cell_phase_dec();
        grid_sync_sw();

        // 7: tmp = relu(h @ W_dec^T + b_dec)  [64 tiles of 32x64]
        if (bid < 64) {
            gemm_tile32(g_h, HH, W_dec, HH, 0, HH,
                        b_dec, g_tmp, HH, 1,
                        (bid >> 4) * 32, (bid & 15) * 64, As, Bs);
        }
        grid_sync_sw();

        // 8: out[s] = tmp @ W_out^T + b_out  [16 tiles of 32x64]
        if (bid < 16) {
            gemm_tile32(g_tmp, HH, W_out, HH, 0, HH,
                        b_out, out + (size_t)s * BB * OO, OO, 0,
                        (bid >> 2) * 32, (bid & 3) * 64, As, Bs);
        }
        grid_sync_sw();
    }
}

// ---------------- host orchestration: 4 graph nodes ----------------
extern "C" void kernel_launch(void* const* d_in, const int* in_sizes, int n_in,
                              void* d_out, int out_size)
{
    const float* input_seq = (const float*)d_in[0];
    const float* W_ih_enc  = (const float*)d_in[1];
    const float* W_hh_enc  = (const float*)d_in[2];
    const float* b_ih_enc  = (const float*)d_in[3];
    const float* b_hh_enc  = (const float*)d_in[4];
    const float* W_attn    = (const float*)d_in[5];
    const float* b_attn    = (const float*)d_in[6];
    const float* v         = (const float*)d_in[7];
    const float* W_ih_dec  = (const float*)d_in[8];
    const float* W_hh_dec  = (const float*)d_in[9];
    const float* b_ih_dec  = (const float*)d_in[10];
    const float* b_hh_dec  = (const float*)d_in[11];
    const float* W_dec     = (const float*)d_in[12];
    const float* b_dec     = (const float*)d_in[13];
    const float* W_out     = (const float*)d_in[14];
    const float* b_out     = (const float*)d_in[15];
    float* out = (float*)d_out;

    const int len_out = out_size / (BB * OO);  // 30

    float *p_xw, *p_ctx_seq, *p_ctx_proj;
    cudaGetSymbolAddress((void**)&p_xw, g_xw);
    cudaGetSymbolAddress((void**)&p_ctx_seq, g_ctx_seq);
    cudaGetSymbolAddress((void**)&p_ctx_proj, g_ctx_proj);

    // 1) xW = input_seq @ W_ih_enc^T + b_ih_enc + b_hh_enc  (fully parallel)
    par_gemm<<<dim3(GG / 64, (TT * BB) / 64), 256>>>(
        input_seq, II, W_ih_enc, II, 0, II, b_ih_enc, b_hh_enc, p_xw, GG);

    // 2) persistent encoder: 512 x (h@W_hh + fused cell)
    encoder_kernel<<<NB, 512>>>(W_hh_enc, b_ih_dec, b_hh_dec);

    // 3) ctx_proj = ctx_seq @ W_c^T + b_attn
    par_gemm<<<dim3(HH / 64, (TT * BB) / 64), 256>>>(
        p_ctx_seq, HH, W_attn, 2 * HH, HH, HH, b_attn, nullptr, p_ctx_proj, HH);

    // 4) persistent decoder
    decoder_kernel<<<NB, 256>>>(W_attn, v, W_ih_dec, W_hh_dec,
                                W_dec, b_dec, W_out, b_out, out, len_out);
}

// round 9
// speedup vs baseline: 1.7400x; 1.7400x over previous
#include <cuda_runtime.h>
#include <math.h>

#define TT 512
#define BB 128
#define II 256
#define HH 1024
#define OO 256
#define GG 4096   // 4*H
#define NB 128    // persistent blocks (<= 148 SMs -> single wave)

// ---------------- device scratch (static, graph-safe) ----------------
__device__ float g_h[BB * HH];
__device__ float g_c[BB * HH];
__device__ float g_gates[BB * GG];
__device__ float g_tmp[BB * HH];
__device__ float g_context[BB * HH];
__device__ float g_hWh[BB * HH];
__device__ float g_scores[TT * BB];
__device__ float g_wts[TT * BB];
__device__ float g_bias_dec[GG];
__device__ float g_ctx_seq[(size_t)TT * BB * HH];   // 268 MB
__device__ float g_ctx_proj[(size_t)TT * BB * HH];  // 268 MB
__device__ float g_xw[(size_t)TT * BB * GG];        // 1.07 GB: x@W_ih^T + biases

// ---------------- packed f32x2 helpers (Blackwell double-pumped fp32) ----------
#define PACK2(d, s)      asm("mov.b64 %0, {%1, %1};" : "=l"(d) : "f"(s))
#define FMA2(acc, a, b)  asm("fma.rn.f32x2 %0, %1, %2, %0;" : "+l"(acc) : "l"(a), "l"(b))
#define UNPK2(lo, hi, v) asm("mov.b64 {%0, %1}, %2;" : "=f"(lo), "=f"(hi) : "l"(v))

// fast tanh: 1 - 2/(exp(2x)+1)  via ex2.approx + rcp.approx (abs err ~1e-7)
__device__ __forceinline__ float ftanh(float x)
{
    float e, r;
    asm("ex2.approx.f32 %0, %1;" : "=f"(e) : "f"(x * 2.8853900817779268f));
    asm("rcp.approx.f32 %0, %1;" : "=f"(r) : "f"(e + 1.0f));
    return fmaf(-2.0f, r, 1.0f);
}

// fast sigmoid: 1/(1+exp(-x)) via ex2.approx + rcp.approx (abs err ~1e-7)
__device__ __forceinline__ float fsig(float x)
{
    float e, r;
    asm("ex2.approx.f32 %0, %1;" : "=f"(e) : "f"(x * -1.4426950408889634f));
    asm("rcp.approx.f32 %0, %1;" : "=f"(r) : "f"(e + 1.0f));
    return r;
}

// ---------------- software grid barrier ----------------
__device__ int g_bar_count;
__device__ int g_bar_gen;

__device__ __forceinline__ void grid_sync_sw()
{
    __syncthreads();
    if (threadIdx.x == 0) {
        int gen = *(volatile int*)&g_bar_gen;   // read before arriving
        __threadfence();
        if (atomicAdd(&g_bar_count, 1) == NB - 1) {
            g_bar_count = 0;
            __threadfence();
            atomicExch(&g_bar_gen, gen + 1);
        } else {
            while (*(volatile int*)&g_bar_gen == gen) { __nanosleep(32); }
        }
    }
    __syncthreads();
}

// =====================================================================
// Parallel GEMM: C = A @ W^T (+bias1)(+bias2), 64x64 tiles, 256 thr, f32x2
// W row n is W[n*ldw + woff ... +K]. K % 16 == 0.   (R5 structure)
// =====================================================================
__global__ __launch_bounds__(256) void par_gemm(
    const float* __restrict__ A, int lda,
    const float* __restrict__ W, int ldw, int woff, int K,
    const float* __restrict__ bias1, const float* __restrict__ bias2,
    float* __restrict__ C, int ldc)
{
    __shared__ __align__(16) float As[16][68];
    __shared__ __align__(16) float Bs[16][68];
    const int tid  = threadIdx.x;
    const int tx   = tid & 15;
    const int ty   = tid >> 4;
    const int bn   = blockIdx.x * 64;
    const int bm   = blockIdx.y * 64;
    const int lrow = tid >> 2;
    const int lcol = (tid & 3) << 2;

    unsigned long long acc2[4][2] = {};

    for (int k0 = 0; k0 < K; k0 += 16) {
        float4 av = *(const float4*)(A + (size_t)(bm + lrow) * lda + k0 + lcol);
        float4 wv = *(const float4*)(W + (size_t)(bn + lrow) * ldw + woff + k0 + lcol);
        __syncthreads();
        As[lcol + 0][lrow] = av.x; As[lcol + 1][lrow] = av.y;
        As[lcol + 2][lrow] = av.z; As[lcol + 3][lrow] = av.w;
        Bs[lcol + 0][lrow] = wv.x; Bs[lcol + 1][lrow] = wv.y;
        Bs[lcol + 2][lrow] = wv.z; Bs[lcol + 3][lrow] = wv.w;
        __syncthreads();
        #pragma unroll
        for (int kk = 0; kk < 16; ++kk) {
            float4 a = *(const float4*)&As[kk][ty << 2];
            ulonglong2 b = *(const ulonglong2*)&Bs[kk][tx << 2];
            unsigned long long aa;
            PACK2(aa, a.x); FMA2(acc2[0][0], aa, b.x); FMA2(acc2[0][1], aa, b.y);
            PACK2(aa, a.y); FMA2(acc2[1][0], aa, b.x); FMA2(acc2[1][1], aa, b.y);
            PACK2(aa, a.z); FMA2(acc2[2][0], aa, b.x); FMA2(acc2[2][1], aa, b.y);
            PACK2(aa, a.w); FMA2(acc2[3][0], aa, b.x); FMA2(acc2[3][1], aa, b.y);
        }
    }

    const int m0 = bm + (ty << 2);
    const int n0 = bn + (tx << 2);
    float4 bv = make_float4(0.f, 0.f, 0.f, 0.f);
    if (bias1) {
        float4 b1 = *(const float4*)(bias1 + n0);
        bv.x += b1.x; bv.y += b1.y; bv.z += b1.z; bv.w += b1.w;
    }
    if (bias2) {
        float4 b2 = *(const float4*)(bias2 + n0);
        bv.x += b2.x; bv.y += b2.y; bv.z += b2.z; bv.w += b2.w;
    }
    #pragma unroll
    for (int i = 0; i < 4; ++i) {
        float4 r;
        UNPK2(r.x, r.y, acc2[i][0]);
        UNPK2(r.z, r.w, acc2[i][1]);
        r.x += bv.x; r.y += bv.y; r.z += bv.z; r.w += bv.w;
        *(float4*)(C + (size_t)(m0 + i) * ldc + n0) = r;
    }
}

// =====================================================================
// Persistent encoder: 512 steps of h@W_hh + fused LSTM cell.
// Block tile: 32 batch rows x 32 h-cols x 4 gates. 128 blocks, 512 thr.
// (R5 structure; cell uses MUFU transcendentals)
// =====================================================================
__global__ __launch_bounds__(512) void encoder_kernel(
    const float* __restrict__ W_hh,
    const float* __restrict__ bihd, const float* __restrict__ bhhd)
{
    __shared__ __align__(16) float As[2][16][34];   // [buf][k][m]
    __shared__ __align__(16) float Bs[2][16][132];  // [buf][k][n] n=4gates*32
    __shared__ __align__(16) float Gs[32][132];     // gate tile for cell

    const int tid = threadIdx.x;
    const int bid = blockIdx.x;

    for (int i = bid * 512 + tid; i < BB * HH; i += NB * 512) { g_h[i] = 0.f; g_c[i] = 0.f; }
    for (int i = bid * 512 + tid; i < GG; i += NB * 512) g_bias_dec[i] = bihd[i] + bhhd[i];
    grid_sync_sw();

    const int bm  = (bid >> 5) * 32;   // 4 batch groups
    const int hh0 = (bid & 31) * 32;   // 32 h-col groups
    const int tx  = tid & 31;          // n float4 index: n0 = tx*4
    const int ty  = tid >> 5;          // 0..15: m rows 2ty, 2ty+1

    const int ln = tid >> 2;                         // 0..127
    const int lk = (tid & 3) << 2;                   // 0,4,8,12
    const float* wbase = W_hh + (size_t)((ln >> 5) * HH + hh0 + (ln & 31)) * HH + lk;
    const int arow = tid >> 2;
    const float* abase = g_h + (size_t)(bm + arow) * HH + lk;

    const int n0 = tx << 2;
    const int gate = n0 >> 5;
    const int within = n0 & 31;
    const size_t xwcol = (size_t)gate * HH + hh0 + within;

    for (int t = 0; t < TT; ++t) {
        float4 wv = *(const float4*)(wbase);
        float4 av = (tid < 128) ? *(const float4*)(abase) : make_float4(0, 0, 0, 0);

        unsigned long long acc2[2][2] = {};
        int buf = 0;
        {
            Bs[0][lk + 0][ln] = wv.x; Bs[0][lk + 1][ln] = wv.y;
            Bs[0][lk + 2][ln] = wv.z; Bs[0][lk + 3][ln] = wv.w;
            if (tid < 128) {
                As[0][lk + 0][arow] = av.x; As[0][lk + 1][arow] = av.y;
                As[0][lk + 2][arow] = av.z; As[0][lk + 3][arow] = av.w;
            }
        }
        __syncthreads();

        #pragma unroll 1
        for (int kt = 0; kt < 64; ++kt) {
            if (kt < 63) {
                wv = *(const float4*)(wbase + (kt + 1) * 16);
                if (tid < 128) av = *(const float4*)(abase + (kt + 1) * 16);
            }
            const float* ap = &As[buf][0][ty << 1];
            const float* bp = &Bs[buf][0][n0];
            #pragma unroll
            for (int kk = 0; kk < 16; ++kk) {
                float2 a = *(const float2*)(ap + kk * 34);
                ulonglong2 b = *(const ulonglong2*)(bp + kk * 132);
                unsigned long long aa;
                PACK2(aa, a.x); FMA2(acc2[0][0], aa, b.x); FMA2(acc2[0][1], aa, b.y);
                PACK2(aa, a.y); FMA2(acc2[1][0], aa, b.x); FMA2(acc2[1][1], aa, b.y);
            }
            if (kt < 63) {
                buf ^= 1;
                Bs[buf][lk + 0][ln] = wv.x; Bs[buf][lk + 1][ln] = wv.y;
                Bs[buf][lk + 2][ln] = wv.z; Bs[buf][lk + 3][ln] = wv.w;
                if (tid < 128) {
                    As[buf][lk + 0][arow] = av.x; As[buf][lk + 1][arow] = av.y;
                    As[buf][lk + 2][arow] = av.z; As[buf][lk + 3][arow] = av.w;
                }
                __syncthreads();
            }
        }

        // epilogue: add precomputed xW (biases folded), stage gates
        {
            const float* xwp = g_xw + ((size_t)t * BB + bm) * GG + xwcol;
            #pragma unroll
            for (int i = 0; i < 2; ++i) {
                int m = (ty << 1) + i;
                float4 x4 = *(const float4*)(xwp + (size_t)m * GG);
                float4 r;
                UNPK2(r.x, r.y, acc2[i][0]);
                UNPK2(r.z, r.w, acc2[i][1]);
                r.x += x4.x; r.y += x4.y; r.z += x4.z; r.w += x4.w;
                *(float4*)&Gs[m][n0] = r;
            }
        }
        __syncthreads();

        // fused LSTM cell (MUFU transcendentals)
        #pragma unroll
        for (int e = tid; e < 32 * 32; e += 512) {
            int r = e >> 5, hc = e & 31;
            float gi = fsig(Gs[r][hc]);
            float gf = fsig(Gs[r][32 + hc]);
            float gg = ftanh(Gs[r][64 + hc]);
            float go = fsig(Gs[r][96 + hc]);
            size_t idx = (size_t)(bm + r) * HH + hh0 + hc;
            float c = gf * g_c[idx] + gi * gg;
            g_c[idx] = c;
            float h = go * ftanh(c);
            g_h[idx] = h;
            g_ctx_seq[(size_t)t * BB * HH + idx] = h;
        }
        grid_sync_sw();
    }
}

// =====================================================================
// Dual-input 64x64 GEMM tile (decoder), 256 threads, f32x2 (R5 structure)
// =====================================================================
__device__ __forceinline__ void gemm_tile(
    const float* __restrict__ A1, int lda1,
    const float* __restrict__ W1, int ldw1, int woff1, int K1,
    const float* __restrict__ A2, int lda2,
    const float* __restrict__ W2, int ldw2, int woff2, int K2,
    const float* __restrict__ bias,
    float* __restrict__ C, int ldc, int do_relu,
    int bm, int bn, float (&As)[16][68], float (&Bs)[16][68])
{
    const int tid  = threadIdx.x;
    const int tx   = tid & 15;
    const int ty   = tid >> 4;
    const int lrow = tid >> 2;
    const int lcol = (tid & 3) << 2;

    unsigned long long acc2[4][2] = {};

    #pragma unroll 1
    for (int ph = 0; ph < 2; ++ph) {
        const float* A  = ph ? A2 : A1;
        const float* W  = ph ? W2 : W1;
        const int lda   = ph ? lda2 : lda1;
        const int ldw   = ph ? ldw2 : ldw1;
        const int woff  = ph ? woff2 : woff1;
        const int K     = ph ? K2 : K1;

        for (int k0 = 0; k0 < K; k0 += 16) {
            float4 av = *(const float4*)(A + (size_t)(bm + lrow) * lda + k0 + lcol);
            float4 wv = *(const float4*)(W + (size_t)(bn + lrow) * ldw + woff + k0 + lcol);
            __syncthreads();
            As[lcol + 0][lrow] = av.x; As[lcol + 1][lrow] = av.y;
            As[lcol + 2][lrow] = av.z; As[lcol + 3][lrow] = av.w;
            Bs[lcol + 0][lrow] = wv.x; Bs[lcol + 1][lrow] = wv.y;
            Bs[lcol + 2][lrow] = wv.z; Bs[lcol + 3][lrow] = wv.w;
            __syncthreads();
            #pragma unroll
            for (int kk = 0; kk < 16; ++kk) {
                float4 a = *(const float4*)&As[kk][ty << 2];
                ulonglong2 b = *(const ulonglong2*)&Bs[kk][tx << 2];
                unsigned long long aa;
                PACK2(aa, a.x); FMA2(acc2[0][0], aa, b.x); FMA2(acc2[0][1], aa, b.y);
                PACK2(aa, a.y); FMA2(acc2[1][0], aa, b.x); FMA2(acc2[1][1], aa, b.y);
                PACK2(aa, a.z); FMA2(acc2[2][0], aa, b.x); FMA2(acc2[2][1], aa, b.y);
                PACK2(aa, a.w); FMA2(acc2[3][0], aa, b.x); FMA2(acc2[3][1], aa, b.y);
            }
        }
    }

    const int m0 = bm + (ty << 2);
    const int n0 = bn + (tx << 2);
    float4 bv = bias ? *(const float4*)(bias + n0) : make_float4(0.f, 0.f, 0.f, 0.f);
    #pragma unroll
    for (int i = 0; i < 4; ++i) {
        float4 r;
        UNPK2(r.x, r.y, acc2[i][0]);
        UNPK2(r.z, r.w, acc2[i][1]);
        r.x += bv.x; r.y += bv.y; r.z += bv.z; r.w += bv.w;
        if (do_relu) {
            r.x = fmaxf(r.x, 0.f); r.y = fmaxf(r.y, 0.f);
            r.z = fmaxf(r.z, 0.f); r.w = fmaxf(r.w, 0.f);
        }
        *(float4*)(C + (size_t)(m0 + i) * ldc + n0) = r;
    }
}

// LSTM cell (decoder), MUFU transcendentals
__device__ __forceinline__ void cell_phase_dec()
{
    for (int idx = blockIdx.x * 256 + threadIdx.x; idx < BB * HH; idx += NB * 256) {
        int b  = idx >> 10;
        int hh = idx & (HH - 1);
        const float* gb = g_gates + (size_t)b * GG;
        float i = fsig(gb[hh]);
        float f = fsig(gb[HH + hh]);
        float g = ftanh(gb[2 * HH + hh]);
        float o = fsig(gb[3 * HH + hh]);
        float c = f * g_c[idx] + i * g;
        g_c[idx] = c;
        g_h[idx] = o * ftanh(c);
    }
}

// =====================================================================
// Persistent decoder. 128 blocks, 256 threads. (R5 structure + ftanh scores)
// =====================================================================
__global__ __launch_bounds__(256) void decoder_kernel(
    const float* __restrict__ W_attn, const float* __restrict__ v,
    const float* __restrict__ W_ih_dec, const float* __restrict__ W_hh_dec,
    const float* __restrict__ W_dec, const float* __restrict__ b_dec,
    const float* __restrict__ W_out, const float* __restrict__ b_out,
    float* __restrict__ out, int len_out)
{
    __shared__ __align__(16) float As[16][68];
    __shared__ __align__(16) float Bs[16][68];
    __shared__ float red[TT];
    const int bid = blockIdx.x;
    const int tid = threadIdx.x;

    for (int i = bid * 256 + tid; i < BB * HH; i += NB * 256) g_c[i] = 0.f;
    grid_sync_sw();

    for (int s = 0; s < len_out; ++s) {
        // 1: hWh = h @ W_h^T  [32 tiles]
        if (bid < 32) {
            gemm_tile(g_h, HH, W_attn, 2 * HH, 0, HH,
                      nullptr, 0, nullptr, 0, 0, 0,
                      nullptr, g_hWh, HH, 0, (bid >> 4) * 64, (bid & 15) * 64, As, Bs);
        }
        grid_sync_sw();

        // 2: scores[t,b] = sum_g ftanh(hWh[b,g]+ctx_proj[t,b,g]) * v[g]
        {
            int w = bid * 8 + (tid >> 5);
            int lane = tid & 31;
            for (int p = w; p < TT * BB; p += NB * 8) {
                int t = p >> 7, b = p & (BB - 1);
                const float* cp = g_ctx_proj + ((size_t)t * BB + b) * HH;
                const float* hw = g_hWh + (size_t)b * HH;
                float sum = 0.f;
                #pragma unroll 2
                for (int g = lane * 4; g < HH; g += 128) {
                    float4 c4 = *(const float4*)(cp + g);
                    float4 h4 = *(const float4*)(hw + g);
                    float4 v4 = *(const float4*)(v + g);
                    sum += ftanh(h4.x + c4.x) * v4.x;
                    sum += ftanh(h4.y + c4.y) * v4.y;
                    sum += ftanh(h4.z + c4.z) * v4.z;
                    sum += ftanh(h4.w + c4.w) * v4.w;
                }
                #pragma unroll
                for (int off = 16; off; off >>= 1)
                    sum += __shfl_down_sync(0xffffffffu, sum, off);
                if (lane == 0) g_scores[p] = sum;
            }
        }
        grid_sync_sw();

        // 3: softmax over t (column b = bid)
        {
            float a  = g_scores[tid * BB + bid];
            float a2 = g_scores[(tid + 256) * BB + bid];
            red[tid] = fmaxf(a, a2);
            __syncthreads();
            for (int off = 128; off; off >>= 1) {
                if (tid < off) red[tid] = fmaxf(red[tid], red[tid + off]);
                __syncthreads();
            }
            float mx = red[0];
            __syncthreads();
            float e1 = expf(a - mx), e2 = expf(a2 - mx);
            red[tid] = e1 + e2;
            __syncthreads();
            for (int off = 128; off; off >>= 1) {
                if (tid < off) red[tid] += red[tid + off];
                __syncthreads();
            }
            float inv = 1.f / red[0];
            g_wts[tid * BB + bid] = e1 * inv;
            g_wts[(tid + 256) * BB + bid] = e2 * inv;
            __syncthreads();
        }
        grid_sync_sw();

        // 4: context[b,h] = sum_t ctx_seq[t,b,h]*w[t,b]; block bid owns b=bid
        {
            for (int t = tid; t < TT; t += 256) red[t] = g_wts[t * BB + bid];
            __syncthreads();
            const int hh = tid * 4;
            const float* base = g_ctx_seq + (size_t)bid * HH + hh;
            float4 sacc = make_float4(0.f, 0.f, 0.f, 0.f);
            #pragma unroll 4
            for (int t = 0; t < TT; ++t) {
                float4 x = *(const float4*)(base + (size_t)t * BB * HH);
                float wt = red[t];
                sacc.x += x.x * wt; sacc.y += x.y * wt;
                sacc.z += x.z * wt; sacc.w += x.w * wt;
            }
            *(float4*)(g_context + bid * HH + hh) = sacc;
            __syncthreads();
        }
        grid_sync_sw();

        // 5: gates = context@W_ih_dec^T + h@W_hh_dec^T + bias  [128 tiles]
        gemm_tile(g_context, HH, W_ih_dec, HH, 0, HH,
                  g_h, HH, W_hh_dec, HH, 0, HH,
                  g_bias_dec, g_gates, GG, 0, (bid >> 6) * 64, (bid & 63) * 64, As, Bs);
        grid_sync_sw();

        // 6: LSTM cell
        cell_phase_dec();
        grid_sync_sw();

        // 7: tmp = relu(h @ W_dec^T + b_dec)  [32 tiles]
        if (bid < 32) {
            gemm_tile(g_h, HH, W_dec, HH, 0, HH,
                      nullptr, 0, nullptr, 0, 0, 0,
                      b_dec, g_tmp, HH, 1, (bid >> 4) * 64, (bid & 15) * 64, As, Bs);
        }
        grid_sync_sw();

        // 8: out[s] = tmp @ W_out^T + b_out  [8 tiles]
        if (bid < 8) {
            gemm_tile(g_tmp, HH, W_out, HH, 0, HH,
                      nullptr, 0, nullptr, 0, 0, 0,
                      b_out, out + (size_t)s * BB * OO, OO, 0,
                      (bid >> 2) * 64, (bid & 3) * 64, As, Bs);
        }
        grid_sync_sw();
    }
}

// ---------------- host orchestration: 4 graph nodes ----------------
extern "C" void kernel_launch(void* const* d_in, const int* in_sizes, int n_in,
                              void* d_out, int out_size)
{
    const float* input_seq = (const float*)d_in[0];
    const float* W_ih_enc  = (const float*)d_in[1];
    const float* W_hh_enc  = (const float*)d_in[2];
    const float* b_ih_enc  = (const float*)d_in[3];
    const float* b_hh_enc  = (const float*)d_in[4];
    const float* W_attn    = (const float*)d_in[5];
    const float* b_attn    = (const float*)d_in[6];
    const float* v         = (const float*)d_in[7];
    const float* W_ih_dec  = (const float*)d_in[8];
    const float* W_hh_dec  = (const float*)d_in[9];
    const float* b_ih_dec  = (const float*)d_in[10];
    const float* b_hh_dec  = (const float*)d_in[11];
    const float* W_dec     = (const float*)d_in[12];
    const float* b_dec     = (const float*)d_in[13];
    const float* W_out     = (const float*)d_in[14];
    const float* b_out     = (const float*)d_in[15];
    float* out = (float*)d_out;

    const int len_out = out_size / (BB * OO);  // 30

    float *p_xw, *p_ctx_seq, *p_ctx_proj;
    cudaGetSymbolAddress((void**)&p_xw, g_xw);
    cudaGetSymbolAddress((void**)&p_ctx_seq, g_ctx_seq);
    cudaGetSymbolAddress((void**)&p_ctx_proj, g_ctx_proj);

    // 1) xW = input_seq @ W_ih_enc^T + b_ih_enc + b_hh_enc  (fully parallel)
    par_gemm<<<dim3(GG / 64, (TT * BB) / 64), 256>>>(
        input_seq, II, W_ih_enc, II, 0, II, b_ih_enc, b_hh_enc, p_xw, GG);

    // 2) persistent encoder: 512 x (h@W_hh + fused cell)
    encoder_kernel<<<NB, 512>>>(W_hh_enc, b_ih_dec, b_hh_dec);

    // 3) ctx_proj = ctx_seq @ W_c^T + b_attn
    par_gemm<<<dim3(HH / 64, (TT * BB) / 64), 256>>>(
        p_ctx_seq, HH, W_attn, 2 * HH, HH, HH, b_attn, nullptr, p_ctx_proj, HH);

    // 4) persistent decoder
    decoder_kernel<<<NB, 256>>>(W_attn, v, W_ih_dec, W_hh_dec,
                                W_dec, b_dec, W_out, b_out, out, len_out);
}